// round 5
// baseline (speedup 1.0000x reference)
#include <cuda_runtime.h>
#include <cstdint>

#define N_NODES  10000
#define N_EDGES  320000
#define N_GRAPHS 16
#define D_IN     256
#define D_H      64

// ---------------- device scratch (no allocations allowed) ----------------
__device__ float g_S[N_NODES * D_H];       // self projection (+bias)
__device__ float g_X[N_NODES * D_H];       // neighbor projection
__device__ float g_h1[N_NODES * D_H];      // layer1 output
__device__ float g_h2[N_NODES * D_H];      // layer2 output
__device__ int   g_rowcnt[N_NODES];        // in-degree histogram
__device__ int   g_rowptr[N_NODES + 1];    // CSR row pointers (by dst)
__device__ int   g_cursor[N_NODES];        // placement cursors
__device__ int   g_csr[N_EDGES];           // CSR column indices (src)

// ---------------- small helpers ----------------

__device__ __forceinline__ unsigned long long pack2(float lo, float hi) {
    unsigned long long r;
    asm("mov.b64 %0, {%1, %2};" : "=l"(r) : "f"(lo), "f"(hi));
    return r;
}
__device__ __forceinline__ float2 unpack2(unsigned long long v) {
    float2 r;
    asm("mov.b64 {%0, %1}, %2;" : "=f"(r.x), "=f"(r.y) : "l"(v));
    return r;
}
__device__ __forceinline__ void ffma2(unsigned long long& d,
                                      unsigned long long a,
                                      unsigned long long b) {
    asm("fma.rn.f32x2 %0, %1, %2, %0;" : "+l"(d) : "l"(a), "l"(b));
}

__device__ __forceinline__ int warp_incl_scan(int v) {
    int lane = threadIdx.x & 31;
#pragma unroll
    for (int o = 1; o < 32; o <<= 1) {
        int n = __shfl_up_sync(0xffffffffu, v, o);
        if (lane >= o) v += n;
    }
    return v;
}

// ---------------- CSR build ----------------

__global__ void hist_kernel(const int* __restrict__ dst) {
    int t = blockIdx.x * blockDim.x + threadIdx.x;
    if (t * 4 >= N_EDGES) return;
    int4 d4 = *reinterpret_cast<const int4*>(dst + t * 4);
    atomicAdd(&g_rowcnt[d4.x], 1);
    atomicAdd(&g_rowcnt[d4.y], 1);
    atomicAdd(&g_rowcnt[d4.z], 1);
    atomicAdd(&g_rowcnt[d4.w], 1);
}

// single-block prefix sum over 10000 counts -> rowptr, cursor
__global__ void scan_kernel() {
    __shared__ int wsum[32];
    __shared__ int s_total;
    int tid  = threadIdx.x;
    int lane = tid & 31;
    int wid  = tid >> 5;
    int running = 0;

    for (int chunk = 0; chunk < (N_NODES + 1023) / 1024; chunk++) {
        int i = chunk * 1024 + tid;
        int v = (i < N_NODES) ? g_rowcnt[i] : 0;
        int incl = warp_incl_scan(v);
        if (lane == 31) wsum[wid] = incl;
        __syncthreads();
        if (wid == 0) {
            int wv = wsum[lane];
            int wincl = warp_incl_scan(wv);
            wsum[lane] = wincl;
            if (lane == 31) s_total = wincl;
        }
        __syncthreads();
        int base = (wid > 0) ? wsum[wid - 1] : 0;
        incl += base;
        if (i < N_NODES) {
            g_rowptr[i + 1] = running + incl;
            g_cursor[i]     = running + incl - v;
        }
        if (tid == 0 && chunk == 0) g_rowptr[0] = 0;
        running += s_total;
        __syncthreads();
    }
}

__global__ void place_kernel(const int* __restrict__ src,
                             const int* __restrict__ dst) {
    int t = blockIdx.x * blockDim.x + threadIdx.x;
    if (t * 4 >= N_EDGES) return;
    int4 s4 = *reinterpret_cast<const int4*>(src + t * 4);
    int4 d4 = *reinterpret_cast<const int4*>(dst + t * 4);
    g_csr[atomicAdd(&g_cursor[d4.x], 1)] = s4.x;
    g_csr[atomicAdd(&g_cursor[d4.y], 1)] = s4.y;
    g_csr[atomicAdd(&g_cursor[d4.z], 1)] = s4.z;
    g_csr[atomicAdd(&g_cursor[d4.w], 1)] = s4.w;
}

// ---------------- projection: S = A@Wself + b, X = A@Wneigh ----------------
// Warp-autonomous register GEMM: each warp owns 8 rows; all 32 lanes consume
// identical A scalars (uniform-address LDG broadcast), each lane owns one
// column-pair of both W matrices. Register double-buffered software pipeline,
// no shared memory, no __syncthreads.
template <int K>
__global__ void __launch_bounds__(128, 3)
project_kernel(const float* __restrict__ A,
               const float* __restrict__ Wself,
               const float* __restrict__ Wneigh,
               const float* __restrict__ b) {
    const int lane = threadIdx.x & 31;
    const int warp = blockIdx.x * 4 + (threadIdx.x >> 5);
    const int row0 = warp * 8;
    if (row0 >= N_NODES) return;

    const unsigned long long* Ws = reinterpret_cast<const unsigned long long*>(Wself);
    const unsigned long long* Wn = reinterpret_cast<const unsigned long long*>(Wneigh);
    const float* Arow = A + (size_t)row0 * K;

    unsigned long long s2[8], x2[8];
#pragma unroll
    for (int r = 0; r < 8; r++) { s2[r] = 0ull; x2[r] = 0ull; }

    float4 aA[8], aB[8];
    unsigned long long wsA[4], wnA[4], wsB[4], wnB[4];

    auto loadA = [&](float4* buf, int g) {
#pragma unroll
        for (int r = 0; r < 8; r++)
            buf[r] = __ldcs(reinterpret_cast<const float4*>(Arow + r * K + g * 4));
    };
    auto loadW = [&](unsigned long long* ws, unsigned long long* wn, int g) {
#pragma unroll
        for (int j = 0; j < 4; j++) {
            ws[j] = __ldg(&Ws[(g * 4 + j) * 32 + lane]);
            wn[j] = __ldg(&Wn[(g * 4 + j) * 32 + lane]);
        }
    };
    auto compute = [&](const float4* a,
                       const unsigned long long* ws,
                       const unsigned long long* wn) {
#pragma unroll
        for (int kk = 0; kk < 4; kk++) {
#pragma unroll
            for (int r = 0; r < 8; r++) {
                float av = (kk == 0) ? a[r].x : (kk == 1) ? a[r].y
                         : (kk == 2) ? a[r].z : a[r].w;
                unsigned long long a2 = pack2(av, av);
                ffma2(s2[r], a2, ws[kk]);
                ffma2(x2[r], a2, wn[kk]);
            }
        }
    };

    constexpr int NG = K / 4;          // groups of 4 k-values
    loadA(aA, 0);
    loadW(wsA, wnA, 0);
#pragma unroll 1
    for (int g2 = 0; g2 < NG / 2; g2++) {
        loadA(aB, 2 * g2 + 1);
        loadW(wsB, wnB, 2 * g2 + 1);
        compute(aA, wsA, wnA);
        int gn = (2 * g2 + 2 < NG) ? 2 * g2 + 2 : NG - 1;  // clamped overfetch
        loadA(aA, gn);
        loadW(wsA, wnA, gn);
        compute(aB, wsB, wnB);
    }

    float bx = __ldg(b + 2 * lane), by = __ldg(b + 2 * lane + 1);
#pragma unroll
    for (int r = 0; r < 8; r++) {
        int row = row0 + r;
        float2 s = unpack2(s2[r]);
        float2 x = unpack2(x2[r]);
        s.x += bx; s.y += by;
        *reinterpret_cast<float2*>(g_S + row * D_H + 2 * lane) = s;
        *reinterpret_cast<float2*>(g_X + row * D_H + 2 * lane) = x;
    }
}

// ---------------- gather + finalize: out = act(S + mean_{j in N(i)} X_j) ----
template <bool RELU>
__global__ void gather_kernel(float* __restrict__ out) {
    int t    = blockIdx.x * blockDim.x + threadIdx.x;
    int node = t >> 4;
    int lane = t & 15;

    int beg = g_rowptr[node];
    int end = g_rowptr[node + 1];

    float4 acc = make_float4(0.f, 0.f, 0.f, 0.f);
    int p = beg;
    for (; p + 1 < end; p += 2) {
        int s0 = g_csr[p];
        int s1 = g_csr[p + 1];
        float4 v0 = *reinterpret_cast<const float4*>(g_X + s0 * D_H + lane * 4);
        float4 v1 = *reinterpret_cast<const float4*>(g_X + s1 * D_H + lane * 4);
        acc.x += v0.x; acc.y += v0.y; acc.z += v0.z; acc.w += v0.w;
        acc.x += v1.x; acc.y += v1.y; acc.z += v1.z; acc.w += v1.w;
    }
    if (p < end) {
        int s0 = g_csr[p];
        float4 v0 = *reinterpret_cast<const float4*>(g_X + s0 * D_H + lane * 4);
        acc.x += v0.x; acc.y += v0.y; acc.z += v0.z; acc.w += v0.w;
    }

    float inv = 1.f / fmaxf((float)(end - beg), 1.f);
    float4 s4 = *reinterpret_cast<const float4*>(g_S + node * D_H + lane * 4);
    float4 o;
    o.x = s4.x + acc.x * inv;
    o.y = s4.y + acc.y * inv;
    o.z = s4.z + acc.z * inv;
    o.w = s4.w + acc.w * inv;
    if (RELU) {
        o.x = fmaxf(o.x, 0.f); o.y = fmaxf(o.y, 0.f);
        o.z = fmaxf(o.z, 0.f); o.w = fmaxf(o.w, 0.f);
    }
    *reinterpret_cast<float4*>(out + node * D_H + lane * 4) = o;
}

// ---------------- readout + head (graph_id sorted -> contiguous segments) ---
__device__ __forceinline__ int lower_bound_gid(const int* gid, int key) {
    int lo = 0, hi = N_NODES;
    while (lo < hi) {
        int mid = (lo + hi) >> 1;
        if (gid[mid] < key) lo = mid + 1; else hi = mid;
    }
    return lo;
}

__global__ void readout_head_kernel(const float* __restrict__ h,
                                    const int* __restrict__ gid,
                                    const float* __restrict__ Wcls,
                                    const float* __restrict__ bcls,
                                    float* __restrict__ out,
                                    float* __restrict__ out_feat) {
    __shared__ int s_beg, s_end;
    __shared__ float red[4][D_H];
    int g = blockIdx.x;
    if (threadIdx.x == 0) {
        s_beg = lower_bound_gid(gid, g);
        s_end = lower_bound_gid(gid, g + 1);
    }
    __syncthreads();
    int beg = s_beg, end = s_end;
    int c = threadIdx.x & 63;
    int r = threadIdx.x >> 6;   // 0..3

    float acc = 0.f;
    for (int i = beg + r; i < end; i += 4)
        acc += h[i * D_H + c];
    red[r][c] = acc;
    __syncthreads();
    if (r == 0) {
        float m = (red[0][c] + red[1][c] + red[2][c] + red[3][c]) /
                  fmaxf((float)(end - beg), 1.f);
        out_feat[g * D_H + c] = m;
        red[0][c] = m;
    }
    __syncthreads();
    if (threadIdx.x < 2) {
        int j = threadIdx.x;
        float s = bcls[j];
#pragma unroll
        for (int k = 0; k < D_H; k++)
            s = fmaf(red[0][k], Wcls[k * 2 + j], s);
        out[g * 2 + j] = s;
    }
}

// ---------------- launch ----------------

template <typename T>
static T* sym_addr(const void* sym) {
    void* p = nullptr;
    cudaGetSymbolAddress(&p, sym);
    return (T*)p;
}

extern "C" void kernel_launch(void* const* d_in, const int* in_sizes, int n_in,
                              void* d_out, int out_size) {
    const float* feat     = (const float*)d_in[0];
    const int*   src      = (const int*)d_in[1];
    const int*   dst      = (const int*)d_in[2];
    const int*   gid      = (const int*)d_in[3];
    const float* W_self1  = (const float*)d_in[4];
    const float* W_neigh1 = (const float*)d_in[5];
    const float* b1       = (const float*)d_in[6];
    const float* W_self2  = (const float*)d_in[7];
    const float* W_neigh2 = (const float*)d_in[8];
    const float* b2       = (const float*)d_in[9];
    const float* W_self3  = (const float*)d_in[10];
    const float* W_neigh3 = (const float*)d_in[11];
    const float* b3       = (const float*)d_in[12];
    const float* W_cls    = (const float*)d_in[13];
    const float* b_cls    = (const float*)d_in[14];

    float* out      = (float*)d_out;                  // [16, 2]
    float* out_feat = out + N_GRAPHS * 2;             // [16, 64]
    float* h3       = out_feat + N_GRAPHS * D_H;      // [10000, 64]

    float* p_h1 = sym_addr<float>(g_h1);
    float* p_h2 = sym_addr<float>(g_h2);
    int* p_rowcnt = sym_addr<int>(g_rowcnt);

    const int projGrid = (N_NODES / 8 + 3) / 4;       // 313 blocks x 4 warps
    const int edgeGrid = (N_EDGES / 4 + 255) / 256;   // 313
    const int gatherGrid = N_NODES * 16 / 256;        // 625

    // ---- CSR build ----
    cudaMemsetAsync(p_rowcnt, 0, N_NODES * sizeof(int));
    hist_kernel<<<edgeGrid, 256>>>(dst);
    scan_kernel<<<1, 1024>>>();
    place_kernel<<<edgeGrid, 256>>>(src, dst);

    // ---- layer 1 (K=256), relu ----
    project_kernel<D_IN><<<projGrid, 128>>>(feat, W_self1, W_neigh1, b1);
    gather_kernel<true><<<gatherGrid, 256>>>(p_h1);

    // ---- layer 2 (K=64), relu ----
    project_kernel<D_H><<<projGrid, 128>>>(p_h1, W_self2, W_neigh2, b2);
    gather_kernel<true><<<gatherGrid, 256>>>(p_h2);

    // ---- layer 3 (K=64), no relu -> h3 straight into d_out ----
    project_kernel<D_H><<<projGrid, 128>>>(p_h2, W_self3, W_neigh3, b3);
    gather_kernel<false><<<gatherGrid, 256>>>(h3);

    // ---- readout + head ----
    readout_head_kernel<<<N_GRAPHS, 256>>>(h3, gid, W_cls, b_cls, out, out_feat);
}